// round 15
// baseline (speedup 1.0000x reference)
#include <cuda_runtime.h>
#include <cuda_bf16.h>
#include <cuda_fp16.h>
#include <math.h>
#include <cstdint>

// ---------------------------------------------------------------------------
#define B_DIM 4
#define T_DIM 2048
#define C_DIM 2048
#define N_HEAD 16
#define N_KV 4
#define HD 128
#define M_TOT (B_DIM * T_DIM)           // 8192
#define K_DIM 2048
#define NKV_C (N_KV * HD)               // 512
#define NQKV (C_DIM + 2 * NKV_C)        // 3072
#define QK_SCALE 0.08838834764831845f   // 1/sqrt(128)
#define LOG2E 1.4426950408889634f

// ---------------------------------------------------------------------------
// Scratch (static device globals)
// ---------------------------------------------------------------------------
__device__ __half g_xh[(size_t)M_TOT * K_DIM];
__device__ __half g_wqkv[(size_t)NQKV * K_DIM];               // [Wq;Wk;Wv]
__device__ __half g_wo16[(size_t)C_DIM * K_DIM];
__device__ __half g_qh[(size_t)B_DIM * N_HEAD * T_DIM * HD];  // [B,H,T,D]
__device__ __half g_kh[(size_t)B_DIM * N_KV * T_DIM * HD];
__device__ __half g_vh[(size_t)B_DIM * N_KV * T_DIM * HD];
__device__ __half g_ah[(size_t)M_TOT * C_DIM];                // attn out fp16
__device__ float g_cos[(size_t)T_DIM * 64];
__device__ float g_sin[(size_t)T_DIM * 64];

// ---------------------------------------------------------------------------
// Helpers (sm_100-safe)
// ---------------------------------------------------------------------------
__device__ __forceinline__ uint32_t smem_u32(const void* p) {
    uint32_t a;
    asm("{ .reg .u64 t; cvta.to.shared.u64 t, %1; cvt.u32.u64 %0, t; }"
        : "=r"(a) : "l"(p));
    return a;
}
__device__ __forceinline__ void cp_async16(uint32_t dst, const void* src) {
    asm volatile("cp.async.cg.shared.global [%0], [%1], 16;" :: "r"(dst), "l"(src));
}
__device__ __forceinline__ void cp_commit() {
    asm volatile("cp.async.commit_group;" ::: "memory");
}
__device__ __forceinline__ void cp_wait1() {
    asm volatile("cp.async.wait_group 1;" ::: "memory");
}
__device__ __forceinline__ void cp_wait0() {
    asm volatile("cp.async.wait_group 0;" ::: "memory");
}
__device__ __forceinline__ void ldsm4(uint32_t& r0, uint32_t& r1, uint32_t& r2,
                                      uint32_t& r3, uint32_t addr) {
    asm volatile("ldmatrix.sync.aligned.m8n8.x4.shared.b16 {%0,%1,%2,%3}, [%4];"
                 : "=r"(r0), "=r"(r1), "=r"(r2), "=r"(r3) : "r"(addr));
}
__device__ __forceinline__ void ldsm4t(uint32_t& r0, uint32_t& r1, uint32_t& r2,
                                       uint32_t& r3, uint32_t addr) {
    asm volatile("ldmatrix.sync.aligned.m8n8.x4.trans.shared.b16 {%0,%1,%2,%3}, [%4];"
                 : "=r"(r0), "=r"(r1), "=r"(r2), "=r"(r3) : "r"(addr));
}
__device__ __forceinline__ void mma_f16(float* d, const uint32_t* a,
                                        uint32_t b0, uint32_t b1) {
    asm volatile(
        "mma.sync.aligned.m16n8k16.row.col.f32.f16.f16.f32 "
        "{%0,%1,%2,%3}, {%4,%5,%6,%7}, {%8,%9}, {%0,%1,%2,%3};"
        : "+f"(d[0]), "+f"(d[1]), "+f"(d[2]), "+f"(d[3])
        : "r"(a[0]), "r"(a[1]), "r"(a[2]), "r"(a[3]), "r"(b0), "r"(b1));
}
// fast exp2: degree-5 poly, FFMA pipe only (no MUFU)
__device__ __forceinline__ float exp2p(float x) {
    x = fmaxf(x, -126.f);
    float t = rintf(x);
    float f = x - t;
    float p = 0.0013333558f;
    p = fmaf(p, f, 0.0096181291f);
    p = fmaf(p, f, 0.0555041087f);
    p = fmaf(p, f, 0.2402265070f);
    p = fmaf(p, f, 0.6931471806f);
    p = fmaf(p, f, 1.0f);
    return __int_as_float(__float_as_int(p) + (((int)t) << 23));
}
__device__ __forceinline__ uint32_t pack_h2(float x, float y) {
    __half2 h = __floats2half2_rn(x, y);
    return *(uint32_t*)&h;
}
__device__ __forceinline__ uint4 cvt8_f16(const float* src) {
    float4 a = ((const float4*)src)[0], b = ((const float4*)src)[1];
    __half2 h0 = __floats2half2_rn(a.x, a.y);
    __half2 h1 = __floats2half2_rn(a.z, a.w);
    __half2 h2 = __floats2half2_rn(b.x, b.y);
    __half2 h3 = __floats2half2_rn(b.z, b.w);
    uint4 u;
    u.x = *(uint32_t*)&h0; u.y = *(uint32_t*)&h1;
    u.z = *(uint32_t*)&h2; u.w = *(uint32_t*)&h3;
    return u;
}

// ---------------------------------------------------------------------------
// Prep kernels
// ---------------------------------------------------------------------------
__global__ void rope_tables_kernel(const float* __restrict__ rope) {
    int i = blockIdx.x * 256 + threadIdx.x;
    if (i < T_DIM * 64) {
        float sn, cs;
        sincosf(rope[i], &sn, &cs);
        g_sin[i] = sn; g_cos[i] = cs;
    }
}

__global__ void to_f16(const float* __restrict__ src, __half* __restrict__ dst, int n8) {
    int i = blockIdx.x * 256 + threadIdx.x;
    if (i >= n8) return;
    ((uint4*)dst)[i] = cvt8_f16(src + (size_t)i * 8);
}

// Converts Wq,Wk,Wv -> g_wqkv (concatenated rows) and Wo -> g_wo16, one launch.
__global__ void conv_weights(const float* __restrict__ Wq, const float* __restrict__ Wk,
                             const float* __restrict__ Wv, const float* __restrict__ Wo) {
    const int NW1 = (NQKV * K_DIM) / 8;     // 786432
    const int NW2 = (C_DIM * K_DIM) / 8;    // 524288
    int i = blockIdx.x * 256 + threadIdx.x;
    if (i >= NW1 + NW2) return;
    if (i < NW1) {
        size_t e8 = (size_t)i * 8;
        int r = (int)(e8 >> 11);            // row (K_DIM = 2048)
        int cc = (int)(e8 & 2047);
        const float* src;
        if (r < C_DIM)              src = Wq + (size_t)r * K_DIM + cc;
        else if (r < C_DIM + NKV_C) src = Wk + (size_t)(r - C_DIM) * K_DIM + cc;
        else                        src = Wv + (size_t)(r - C_DIM - NKV_C) * K_DIM + cc;
        ((uint4*)g_wqkv)[i] = cvt8_f16(src);
    } else {
        size_t e8 = (size_t)(i - NW1) * 8;
        ((uint4*)g_wo16)[i - NW1] = cvt8_f16(Wo + e8);
    }
}

// ---------------------------------------------------------------------------
// fp16 single-pass NT GEMM: out = A[M,K] @ W[N,K]^T, fp32 accum.
// 128x256 tile/CTA, BK=32, 256 threads = 8 warps (2x4), warp tile 64x64.
// 3-stage cp.async pipeline (dynamic smem, 90KB), ONE __syncthreads per chunk,
// all 16 fragment ldsm issued up-front per chunk (latency hidden by 256 mma).
// 1 CTA/SM (regs ~210). k-accumulation order identical to 128x128 version.
// MODE 4: merged QKV -> g_qh (RoPE+scale) / g_kh (RoPE) / g_vh by n-region.
// MODE 3: O proj -> row-major float [M,N].
// ---------------------------------------------------------------------------
#define GSTR 40
#define A_TILE_B (128 * GSTR * 2)       // 10240
#define B_TILE_B (256 * GSTR * 2)       // 20480
#define STAGE_B (A_TILE_B + B_TILE_B)   // 30720
#define GEMM_SMEM3 (3 * STAGE_B)        // 92160 bytes

template <int MODE>
__global__ __launch_bounds__(256, 1)
void gemm_f16(const __half* __restrict__ A, const __half* __restrict__ W,
              float* __restrict__ outf, int N)
{
    extern __shared__ __align__(16) char smem[];
    const uint32_t sb = smem_u32(smem);

    const int tid = threadIdx.x;
    const int lane = tid & 31;
    const int wid = tid >> 5;
    const int wm = wid >> 2;          // 0..1 (64-row slab)
    const int wn = wid & 3;           // 0..3 (64-col slab)
    const int m0 = blockIdx.y * 128, n0 = blockIdx.x * 256;

    const int NTOT = K_DIM / 32;      // 64

    auto load_chunk = [&](int c) {
        int k0 = c * 32;
        uint32_t st = sb + (uint32_t)(c % 3) * STAGE_B;
        const __half* As = A + (size_t)m0 * K_DIM + k0;
        const __half* Bs = W + (size_t)n0 * K_DIM + k0;
#pragma unroll
        for (int i = 0; i < 6; i++) {
            int idx = tid + i * 256;          // 0..1535
            if (idx < 512) {
                int r = idx >> 2, c4 = idx & 3;
                cp_async16(st + (uint32_t)(r * (GSTR * 2) + c4 * 16),
                           As + (size_t)r * K_DIM + c4 * 8);
            } else {
                int j = idx - 512;            // 0..1023
                int r = j >> 2, c4 = j & 3;
                cp_async16(st + A_TILE_B + (uint32_t)(r * (GSTR * 2) + c4 * 16),
                           Bs + (size_t)r * K_DIM + c4 * 8);
            }
        }
        cp_commit();
    };

    float acc[4][8][4];
#pragma unroll
    for (int mi = 0; mi < 4; mi++)
#pragma unroll
        for (int nf = 0; nf < 8; nf++)
#pragma unroll
            for (int e = 0; e < 4; e++) acc[mi][nf][e] = 0.f;

    const int a_row = lane & 15;
    const int a_col8 = (lane >> 4) * 8;
    const int b_row = (lane & 7) + ((lane & 16) >> 1);
    const int b_col8 = (lane & 8);

    load_chunk(0);
    load_chunk(1);

    for (int c = 0; c < NTOT; c++) {
        if (c + 2 < NTOT) cp_wait1();   // group c complete (c+1 may stay in flight)
        else              cp_wait0();   // tail: drain everything
        __syncthreads();                // buffer c visible; all warps past compute(c-1)
        if (c + 2 < NTOT) load_chunk(c + 2);   // overwrites buffer of chunk c-1 (safe)

        uint32_t st = sb + (uint32_t)(c % 3) * STAGE_B;
        uint32_t aBase = st;
        uint32_t bBase = st + A_TILE_B;

        // ---- issue ALL fragment loads for both k-steps up front ----
        uint32_t a[2][4][4], b[2][4][4];
#pragma unroll
        for (int s = 0; s < 2; s++) {
#pragma unroll
            for (int mi = 0; mi < 4; mi++) {
                uint32_t addr = aBase + (uint32_t)(
                    (wm * 64 + mi * 16 + a_row) * (GSTR * 2) + (s * 16 + a_col8) * 2);
                ldsm4(a[s][mi][0], a[s][mi][1], a[s][mi][2], a[s][mi][3], addr);
            }
#pragma unroll
            for (int nj = 0; nj < 4; nj++) {
                uint32_t addr = bBase + (uint32_t)(
                    (wn * 64 + nj * 16 + b_row) * (GSTR * 2) + (s * 16 + b_col8) * 2);
                ldsm4(b[s][nj][0], b[s][nj][1], b[s][nj][2], b[s][nj][3], addr);
            }
        }

        // ---- 64 mma per warp per chunk (k order: s=0 then s=1) ----
#pragma unroll
        for (int s = 0; s < 2; s++)
#pragma unroll
            for (int mi = 0; mi < 4; mi++)
#pragma unroll
                for (int nj = 0; nj < 4; nj++) {
                    mma_f16(acc[mi][2 * nj],     a[s][mi], b[s][nj][0], b[s][nj][1]);
                    mma_f16(acc[mi][2 * nj + 1], a[s][mi], b[s][nj][2], b[s][nj][3]);
                }
    }

    // epilogue: (e,o) adjacent col pair per acc half
#pragma unroll
    for (int mi = 0; mi < 4; mi++) {
        int r_loc = wm * 64 + mi * 16 + (lane >> 2);
#pragma unroll
        for (int half = 0; half < 2; half++) {
            int mr = m0 + r_loc + half * 8;
            int bb = mr >> 11;
            int t  = mr & (T_DIM - 1);
#pragma unroll
            for (int nf = 0; nf < 8; nf++) {
                int n = n0 + wn * 64 + nf * 8 + (lane & 3) * 2;
                float e = acc[mi][nf][half * 2];
                float o = acc[mi][nf][half * 2 + 1];
                if (MODE == 3) {
                    *(float2*)&outf[(size_t)mr * N + n] = make_float2(e, o);
                } else {
                    // MODE 4: merged QKV
                    if (n < C_DIM) {
                        int hh = n >> 7, d = n & (HD - 1);
                        float cs = g_cos[t * 64 + (d >> 1)];
                        float sn = g_sin[t * 64 + (d >> 1)];
                        float oe = (e * cs - o * sn) * QK_SCALE;
                        float oo = (e * sn + o * cs) * QK_SCALE;
                        *(__half2*)&g_qh[(((size_t)bb * N_HEAD + hh) * T_DIM + t) * HD + d]
                            = __floats2half2_rn(oe, oo);
                    } else if (n < C_DIM + NKV_C) {
                        int nk = n - C_DIM;
                        int hh = nk >> 7, d = nk & (HD - 1);
                        float cs = g_cos[t * 64 + (d >> 1)];
                        float sn = g_sin[t * 64 + (d >> 1)];
                        float oe = e * cs - o * sn;
                        float oo = e * sn + o * cs;
                        *(__half2*)&g_kh[(((size_t)bb * N_KV + hh) * T_DIM + t) * HD + d]
                            = __floats2half2_rn(oe, oo);
                    } else {
                        int nv = n - C_DIM - NKV_C;
                        int hh = nv >> 7, d = nv & (HD - 1);
                        *(__half2*)&g_vh[(((size_t)bb * N_KV + hh) * T_DIM + t) * HD + d]
                            = __floats2half2_rn(e, o);
                    }
                }
            }
        }
    }
}

// ---------------------------------------------------------------------------
// fp16 tensor-core flash attention (FA2) -- unchanged from round 14 (passing).
// ---------------------------------------------------------------------------
#define FSTR 136                      // halves per row
#define FQ_B (128 * FSTR * 2)         // 34816
#define FKV_B (64 * FSTR * 2)         // 17408
#define FL_SMEM (FQ_B + 2 * 2 * FKV_B)  // 104448

__global__ __launch_bounds__(256, 1)
void flash_tc(const int* __restrict__ amask, __half* __restrict__ oh)
{
    extern __shared__ __align__(16) char smem[];
    const uint32_t sb = smem_u32(smem);
    __shared__ uint32_t s_ms[2][2];

    const int tid = threadIdx.x;
    const int lane = tid & 31;
    const int wid = tid >> 5;
    const int qt = gridDim.x - 1 - blockIdx.x;   // LPT: heavy tiles first
    const int h  = blockIdx.y;
    const int b  = blockIdx.z;
    const int kvh = h & (N_KV - 1);

    const __half* qb = g_qh + (((size_t)b * N_HEAD + h) * T_DIM + qt * 128) * HD;
    const __half* kb = g_kh + (((size_t)b * N_KV + kvh) * T_DIM) * HD;
    const __half* vb = g_vh + (((size_t)b * N_KV + kvh) * T_DIM) * HD;

    // ---- stage Q tile ----
#pragma unroll
    for (int i = 0; i < 8; i++) {
        int idx = tid + i * 256;          // 0..2047
        int r = idx >> 4, c16 = idx & 15;
        cp_async16(sb + (uint32_t)(r * (FSTR * 2) + c16 * 16),
                   qb + (size_t)r * HD + c16 * 8);
    }
    cp_commit();

    auto load_tile = [&](int c) {
        uint32_t st = sb + FQ_B + (uint32_t)(c & 1) * (2 * FKV_B);
        const __half* ks = kb + (size_t)c * 64 * HD;
        const __half* vs = vb + (size_t)c * 64 * HD;
#pragma unroll
        for (int i = 0; i < 8; i++) {
            int idx = tid + i * 256;      // 0..2047
            int rem = idx & 1023;
            int r = rem >> 4, c16 = rem & 15;
            const __half* src = (idx < 1024) ? (ks + (size_t)r * HD + c16 * 8)
                                             : (vs + (size_t)r * HD + c16 * 8);
            uint32_t dst = st + (uint32_t)((idx < 1024) ? 0 : FKV_B)
                         + (uint32_t)(r * (FSTR * 2) + c16 * 16);
            cp_async16(dst, src);
        }
        cp_commit();
        if (tid < 64) {
            int v = amask[b * T_DIM + c * 64 + tid];
            uint32_t bal = __ballot_sync(0xffffffffu, v != 0);
            if ((tid & 31) == 0) s_ms[c & 1][tid >> 5] = bal;
        }
    };

    load_tile(0);
    cp_wait0();
    __syncthreads();

    // ---- Q fragments (resident) ----
    uint32_t qa[8][4];
    {
        const int a_row = lane & 15;
        const int a_col8 = (lane >> 4) * 8;
#pragma unroll
        for (int s = 0; s < 8; s++) {
            uint32_t addr = sb + (uint32_t)(
                (wid * 16 + a_row) * (FSTR * 2) + (s * 16 + a_col8) * 2);
            ldsm4(qa[s][0], qa[s][1], qa[s][2], qa[s][3], addr);
        }
    }

    float o[16][4];
#pragma unroll
    for (int nf = 0; nf < 16; nf++)
#pragma unroll
        for (int e = 0; e < 4; e++) o[nf][e] = 0.f;
    float m_i[2] = {-1e30f, -1e30f};
    float l_i[2] = {0.f, 0.f};

    const int b_row = (lane & 7) + ((lane & 16) >> 1);
    const int b_col8 = (lane & 8);
    const int row_in_warp = lane >> 2;
    const int qg_base = qt * 128 + wid * 16 + row_in_warp;   // rows: +0 and +8

    const int nkt = 2 * qt + 2;
    for (int kt = 0; kt < nkt; kt++) {
        cp_wait0();          // tile kt fully resident
        __syncthreads();     // visible to all; all warps past reads of tile kt-1
        if (kt + 1 < nkt) load_tile(kt + 1);   // overwrites kt-1's buffer (safe)

        uint32_t kBase = sb + FQ_B + (uint32_t)(kt & 1) * (2 * FKV_B);
        uint32_t vBase = kBase + FKV_B;

        // ---- S = Q @ K^T : warp computes 16 x 64 ----
        float s[8][4];
#pragma unroll
        for (int nb = 0; nb < 8; nb++)
#pragma unroll
            for (int e = 0; e < 4; e++) s[nb][e] = 0.f;

#pragma unroll
        for (int ks = 0; ks < 8; ks++) {
            uint32_t bb[4][4];
#pragma unroll
            for (int nb2 = 0; nb2 < 4; nb2++) {
                uint32_t addr = kBase + (uint32_t)(
                    (nb2 * 16 + b_row) * (FSTR * 2) + (ks * 16 + b_col8) * 2);
                ldsm4(bb[nb2][0], bb[nb2][1], bb[nb2][2], bb[nb2][3], addr);
            }
#pragma unroll
            for (int nb2 = 0; nb2 < 4; nb2++) {
                mma_f16(s[2 * nb2],     qa[ks], bb[nb2][0], bb[nb2][1]);
                mma_f16(s[2 * nb2 + 1], qa[ks], bb[nb2][2], bb[nb2][3]);
            }
        }

        // ---- mask ----
        const uint32_t w0 = s_ms[kt & 1][0], w1 = s_ms[kt & 1][1];
        const bool diag = (kt >= 2 * qt);
        const bool full_pad = (w0 == 0xffffffffu) && (w1 == 0xffffffffu);
        if (diag || !full_pad) {
#pragma unroll
            for (int nb = 0; nb < 8; nb++)
#pragma unroll
                for (int e = 0; e < 4; e++) {
                    int col = nb * 8 + (lane & 3) * 2 + (e & 1);
                    bool ok = ((col < 32 ? (w0 >> col) : (w1 >> (col - 32))) & 1u) != 0u;
                    if (diag)
                        ok = ok && (kt * 64 + col <= qg_base + (e >> 1) * 8);
                    if (!ok) s[nb][e] = -1e30f;
                }
        }

        // ---- online softmax (rows r and r+8 per thread) ----
        float mx[2] = {-1e30f, -1e30f};
#pragma unroll
        for (int nb = 0; nb < 8; nb++)
#pragma unroll
            for (int e = 0; e < 4; e++) mx[e >> 1] = fmaxf(mx[e >> 1], s[nb][e]);
#pragma unroll
        for (int i = 0; i < 2; i++) {
            mx[i] = fmaxf(mx[i], __shfl_xor_sync(0xffffffffu, mx[i], 1));
            mx[i] = fmaxf(mx[i], __shfl_xor_sync(0xffffffffu, mx[i], 2));
        }
        float alpha[2], rs[2] = {0.f, 0.f};
#pragma unroll
        for (int i = 0; i < 2; i++) {
            float mn = fmaxf(m_i[i], mx[i]);
            alpha[i] = exp2p((m_i[i] - mn) * LOG2E);
            m_i[i] = mn;
        }
#pragma unroll
        for (int nb = 0; nb < 8; nb++)
#pragma unroll
            for (int e = 0; e < 4; e++) {
                float p = exp2p((s[nb][e] - m_i[e >> 1]) * LOG2E);
                s[nb][e] = p;
                rs[e >> 1] += p;
            }
#pragma unroll
        for (int i = 0; i < 2; i++) {
            rs[i] += __shfl_xor_sync(0xffffffffu, rs[i], 1);
            rs[i] += __shfl_xor_sync(0xffffffffu, rs[i], 2);
            l_i[i] = l_i[i] * alpha[i] + rs[i];
        }

        // ---- O *= alpha ----
#pragma unroll
        for (int nf = 0; nf < 16; nf++) {
            o[nf][0] *= alpha[0]; o[nf][1] *= alpha[0];
            o[nf][2] *= alpha[1]; o[nf][3] *= alpha[1];
        }

        // ---- O += P @ V ----
#pragma unroll
        for (int kb = 0; kb < 4; kb++) {
            uint32_t pa[4];
            pa[0] = pack_h2(s[2 * kb][0], s[2 * kb][1]);
            pa[1] = pack_h2(s[2 * kb][2], s[2 * kb][3]);
            pa[2] = pack_h2(s[2 * kb + 1][0], s[2 * kb + 1][1]);
            pa[3] = pack_h2(s[2 * kb + 1][2], s[2 * kb + 1][3]);
#pragma unroll
            for (int nd2 = 0; nd2 < 8; nd2++) {
                uint32_t v0, v1, v2, v3;
                uint32_t addr = vBase + (uint32_t)(
                    (kb * 16 + (lane & 15)) * (FSTR * 2)
                    + (nd2 * 16 + (lane >> 4) * 8) * 2);
                ldsm4t(v0, v1, v2, v3, addr);
                mma_f16(o[2 * nd2],     pa, v0, v1);
                mma_f16(o[2 * nd2 + 1], pa, v2, v3);
            }
        }
    }

    // ---- epilogue: fp16 A for the O-projection ----
    float inv[2] = {1.f / l_i[0], 1.f / l_i[1]};
#pragma unroll
    for (int half = 0; half < 2; half++) {
        size_t row = (size_t)b * T_DIM + qt * 128 + wid * 16 + row_in_warp + half * 8;
#pragma unroll
        for (int nf = 0; nf < 16; nf++) {
            int cc = h * HD + nf * 8 + (lane & 3) * 2;
            *(__half2*)&oh[row * C_DIM + cc] = __floats2half2_rn(
                o[nf][half * 2] * inv[half], o[nf][half * 2 + 1] * inv[half]);
        }
    }
}

// ---------------------------------------------------------------------------
// Launch
// ---------------------------------------------------------------------------
extern "C" void kernel_launch(void* const* d_in, const int* in_sizes, int n_in,
                              void* d_out, int out_size)
{
    const float* x    = (const float*)d_in[0];
    const float* rope = (const float*)d_in[1];
    const int*   am   = (const int*)  d_in[2];
    const float* Wq   = (const float*)d_in[3];
    const float* Wk   = (const float*)d_in[4];
    const float* Wv   = (const float*)d_in[5];
    const float* Wo   = (const float*)d_in[6];
    float* out = (float*)d_out;

    __half *xh, *wqkv, *wo16, *ah;
    cudaGetSymbolAddress((void**)&xh, g_xh);
    cudaGetSymbolAddress((void**)&wqkv, g_wqkv);
    cudaGetSymbolAddress((void**)&wo16, g_wo16);
    cudaGetSymbolAddress((void**)&ah, g_ah);

    cudaFuncSetAttribute(gemm_f16<3>, cudaFuncAttributeMaxDynamicSharedMemorySize, GEMM_SMEM3);
    cudaFuncSetAttribute(gemm_f16<4>, cudaFuncAttributeMaxDynamicSharedMemorySize, GEMM_SMEM3);
    cudaFuncSetAttribute(flash_tc, cudaFuncAttributeMaxDynamicSharedMemorySize, FL_SMEM);

    // prep (launch indices 0..2)
    rope_tables_kernel<<<(T_DIM * 64 + 255) / 256, 256>>>(rope);
    conv_weights<<<((NQKV + C_DIM) * K_DIM / 8 + 255) / 256, 256>>>(Wq, Wk, Wv, Wo);
    to_f16<<<(M_TOT * K_DIM / 8 + 255) / 256, 256>>>(x, xh, M_TOT * K_DIM / 8);

    // merged QKV projection (index 3)
    gemm_f16<4><<<dim3(NQKV / 256, M_TOT / 128), 256, GEMM_SMEM3>>>(xh, wqkv, nullptr, NQKV);

    // attention (index 4)
    flash_tc<<<dim3(T_DIM / 128, N_HEAD, B_DIM), 256, FL_SMEM>>>(am, ah);

    // O projection (index 5 -- ncu -s 5 captures this GEMM)
    gemm_f16<3><<<dim3(C_DIM / 256, M_TOT / 128), 256, GEMM_SMEM3>>>(ah, wo16, out, C_DIM);
}

// round 17
// speedup vs baseline: 1.0899x; 1.0899x over previous
#include <cuda_runtime.h>
#include <cuda_bf16.h>
#include <cuda_fp16.h>
#include <math.h>
#include <cstdint>

// ---------------------------------------------------------------------------
#define B_DIM 4
#define T_DIM 2048
#define C_DIM 2048
#define N_HEAD 16
#define N_KV 4
#define HD 128
#define M_TOT (B_DIM * T_DIM)           // 8192
#define K_DIM 2048
#define NKV_C (N_KV * HD)               // 512
#define NQKV (C_DIM + 2 * NKV_C)        // 3072
#define QK_SCALE 0.08838834764831845f   // 1/sqrt(128)
#define LOG2E 1.4426950408889634f

// ---------------------------------------------------------------------------
// Scratch (static device globals)
// ---------------------------------------------------------------------------
__device__ __half g_xh[(size_t)M_TOT * K_DIM];
__device__ __half g_wqkv[(size_t)NQKV * K_DIM];               // [Wq;Wk;Wv]
__device__ __half g_wo16[(size_t)C_DIM * K_DIM];
__device__ __half g_qh[(size_t)B_DIM * N_HEAD * T_DIM * HD];  // [B,H,T,D]
__device__ __half g_kh[(size_t)B_DIM * N_KV * T_DIM * HD];
__device__ __half g_vh[(size_t)B_DIM * N_KV * T_DIM * HD];
__device__ __half g_ah[(size_t)M_TOT * C_DIM];                // attn out fp16
__device__ float g_cos[(size_t)T_DIM * 64];
__device__ float g_sin[(size_t)T_DIM * 64];

// ---------------------------------------------------------------------------
// Helpers (sm_100-safe)
// ---------------------------------------------------------------------------
__device__ __forceinline__ uint32_t smem_u32(const void* p) {
    uint32_t a;
    asm("{ .reg .u64 t; cvta.to.shared.u64 t, %1; cvt.u32.u64 %0, t; }"
        : "=r"(a) : "l"(p));
    return a;
}
__device__ __forceinline__ void cp_async16(uint32_t dst, const void* src) {
    asm volatile("cp.async.cg.shared.global [%0], [%1], 16;" :: "r"(dst), "l"(src));
}
__device__ __forceinline__ void cp_commit() {
    asm volatile("cp.async.commit_group;" ::: "memory");
}
__device__ __forceinline__ void cp_wait1() {
    asm volatile("cp.async.wait_group 1;" ::: "memory");
}
__device__ __forceinline__ void cp_wait0() {
    asm volatile("cp.async.wait_group 0;" ::: "memory");
}
__device__ __forceinline__ void ldsm4(uint32_t& r0, uint32_t& r1, uint32_t& r2,
                                      uint32_t& r3, uint32_t addr) {
    asm volatile("ldmatrix.sync.aligned.m8n8.x4.shared.b16 {%0,%1,%2,%3}, [%4];"
                 : "=r"(r0), "=r"(r1), "=r"(r2), "=r"(r3) : "r"(addr));
}
__device__ __forceinline__ void ldsm4t(uint32_t& r0, uint32_t& r1, uint32_t& r2,
                                       uint32_t& r3, uint32_t addr) {
    asm volatile("ldmatrix.sync.aligned.m8n8.x4.trans.shared.b16 {%0,%1,%2,%3}, [%4];"
                 : "=r"(r0), "=r"(r1), "=r"(r2), "=r"(r3) : "r"(addr));
}
__device__ __forceinline__ void mma_f16(float* d, const uint32_t* a,
                                        uint32_t b0, uint32_t b1) {
    asm volatile(
        "mma.sync.aligned.m16n8k16.row.col.f32.f16.f16.f32 "
        "{%0,%1,%2,%3}, {%4,%5,%6,%7}, {%8,%9}, {%0,%1,%2,%3};"
        : "+f"(d[0]), "+f"(d[1]), "+f"(d[2]), "+f"(d[3])
        : "r"(a[0]), "r"(a[1]), "r"(a[2]), "r"(a[3]), "r"(b0), "r"(b1));
}
// fast exp2: degree-5 poly, FFMA pipe only (no MUFU)
__device__ __forceinline__ float exp2p(float x) {
    x = fmaxf(x, -126.f);
    float t = rintf(x);
    float f = x - t;
    float p = 0.0013333558f;
    p = fmaf(p, f, 0.0096181291f);
    p = fmaf(p, f, 0.0555041087f);
    p = fmaf(p, f, 0.2402265070f);
    p = fmaf(p, f, 0.6931471806f);
    p = fmaf(p, f, 1.0f);
    return __int_as_float(__float_as_int(p) + (((int)t) << 23));
}
__device__ __forceinline__ uint32_t pack_h2(float x, float y) {
    __half2 h = __floats2half2_rn(x, y);
    return *(uint32_t*)&h;
}
__device__ __forceinline__ uint4 cvt8_f16(const float* src) {
    float4 a = ((const float4*)src)[0], b = ((const float4*)src)[1];
    __half2 h0 = __floats2half2_rn(a.x, a.y);
    __half2 h1 = __floats2half2_rn(a.z, a.w);
    __half2 h2 = __floats2half2_rn(b.x, b.y);
    __half2 h3 = __floats2half2_rn(b.z, b.w);
    uint4 u;
    u.x = *(uint32_t*)&h0; u.y = *(uint32_t*)&h1;
    u.z = *(uint32_t*)&h2; u.w = *(uint32_t*)&h3;
    return u;
}

// ---------------------------------------------------------------------------
// Prep kernels
// ---------------------------------------------------------------------------
__global__ void rope_tables_kernel(const float* __restrict__ rope) {
    int i = blockIdx.x * 256 + threadIdx.x;
    if (i < T_DIM * 64) {
        float sn, cs;
        sincosf(rope[i], &sn, &cs);
        g_sin[i] = sn; g_cos[i] = cs;
    }
}

__global__ void to_f16(const float* __restrict__ src, __half* __restrict__ dst, int n8) {
    int i = blockIdx.x * 256 + threadIdx.x;
    if (i >= n8) return;
    ((uint4*)dst)[i] = cvt8_f16(src + (size_t)i * 8);
}

// Converts Wq,Wk,Wv -> g_wqkv (concatenated rows) and Wo -> g_wo16, one launch.
__global__ void conv_weights(const float* __restrict__ Wq, const float* __restrict__ Wk,
                             const float* __restrict__ Wv, const float* __restrict__ Wo) {
    const int NW1 = (NQKV * K_DIM) / 8;     // 786432
    const int NW2 = (C_DIM * K_DIM) / 8;    // 524288
    int i = blockIdx.x * 256 + threadIdx.x;
    if (i >= NW1 + NW2) return;
    if (i < NW1) {
        size_t e8 = (size_t)i * 8;
        int r = (int)(e8 >> 11);            // row (K_DIM = 2048)
        int cc = (int)(e8 & 2047);
        const float* src;
        if (r < C_DIM)              src = Wq + (size_t)r * K_DIM + cc;
        else if (r < C_DIM + NKV_C) src = Wk + (size_t)(r - C_DIM) * K_DIM + cc;
        else                        src = Wv + (size_t)(r - C_DIM - NKV_C) * K_DIM + cc;
        ((uint4*)g_wqkv)[i] = cvt8_f16(src);
    } else {
        size_t e8 = (size_t)(i - NW1) * 8;
        ((uint4*)g_wo16)[i - NW1] = cvt8_f16(Wo + e8);
    }
}

// ---------------------------------------------------------------------------
// fp16 single-pass NT GEMM: out = A[M,K] @ W[N,K]^T, fp32 accum.
// 128x128 tile/CTA, BK=32, 256 threads = 8 warps (2x4), warp tile 64x32.
// 2 CTAs/SM (regs kept < 128). 3-stage cp.async pipeline, ONE sync per chunk,
// ALL 12 fragment ldsm issued up-front per chunk (latency hidden by 32 mma).
// MODE 4: merged QKV -> g_qh (RoPE+scale) / g_kh (RoPE) / g_vh by n-region.
// MODE 3: O proj -> row-major float [M,N].
// ---------------------------------------------------------------------------
#define GSTR 40
#define TILE_B (128 * GSTR * 2)
#define GEMM_SMEM3 (3 * 2 * TILE_B)     // 61440 bytes

template <int MODE>
__global__ __launch_bounds__(256)
void gemm_f16(const __half* __restrict__ A, const __half* __restrict__ W,
              float* __restrict__ outf, int N)
{
    extern __shared__ __align__(16) char smem[];
    const uint32_t sb = smem_u32(smem);

    const int tid = threadIdx.x;
    const int lane = tid & 31;
    const int wid = tid >> 5;
    const int wm = wid >> 2;
    const int wn = wid & 3;
    const int m0 = blockIdx.y * 128, n0 = blockIdx.x * 128;

    const int NTOT = K_DIM / 32;      // 64

    auto load_chunk = [&](int c) {
        int k0 = c * 32;
        uint32_t st = sb + (uint32_t)(c % 3) * (2 * TILE_B);
        const __half* As = A + (size_t)m0 * K_DIM + k0;
        const __half* Bs = W + (size_t)n0 * K_DIM + k0;
#pragma unroll
        for (int i = 0; i < 4; i++) {
            int idx = tid + i * 256;
            int rem = idx & 511;
            int r = rem >> 2, c4 = rem & 3;
            const __half* src = (idx < 512)
                ? (As + (size_t)r * K_DIM + c4 * 8)
                : (Bs + (size_t)r * K_DIM + c4 * 8);
            uint32_t dst = st + (uint32_t)((idx < 512) ? 0 : TILE_B)
                         + (uint32_t)(r * (GSTR * 2) + c4 * 16);
            cp_async16(dst, src);
        }
        cp_commit();
    };

    float acc[4][4][4];
#pragma unroll
    for (int mi = 0; mi < 4; mi++)
#pragma unroll
        for (int nf = 0; nf < 4; nf++)
#pragma unroll
            for (int e = 0; e < 4; e++) acc[mi][nf][e] = 0.f;

    const int a_row = lane & 15;
    const int a_col8 = (lane >> 4) * 8;
    const int b_row = (lane & 7) + ((lane & 16) >> 1);
    const int b_col8 = (lane & 8);

    load_chunk(0);
    load_chunk(1);

    for (int c = 0; c < NTOT; c++) {
        if (c + 2 < NTOT) cp_wait1();   // group c complete (c+1 may stay in flight)
        else              cp_wait0();   // tail: drain everything
        __syncthreads();                // buffer c visible; all warps past compute(c-1)
        if (c + 2 < NTOT) load_chunk(c + 2);   // overwrites buffer of chunk c-1 (safe)

        uint32_t st = sb + (uint32_t)(c % 3) * (2 * TILE_B);
        uint32_t aBase = st;
        uint32_t bBase = st + TILE_B;

        // ---- issue ALL fragment loads for both k-steps up front ----
        uint32_t a[2][4][4], b[2][2][4];
#pragma unroll
        for (int s = 0; s < 2; s++) {
#pragma unroll
            for (int mi = 0; mi < 4; mi++) {
                uint32_t addr = aBase + (uint32_t)(
                    (wm * 64 + mi * 16 + a_row) * (GSTR * 2) + (s * 16 + a_col8) * 2);
                ldsm4(a[s][mi][0], a[s][mi][1], a[s][mi][2], a[s][mi][3], addr);
            }
#pragma unroll
            for (int nj = 0; nj < 2; nj++) {
                uint32_t addr = bBase + (uint32_t)(
                    (wn * 32 + nj * 16 + b_row) * (GSTR * 2) + (s * 16 + b_col8) * 2);
                ldsm4(b[s][nj][0], b[s][nj][1], b[s][nj][2], b[s][nj][3], addr);
            }
        }

        // ---- 32 mma per warp per chunk (k order: s=0 then s=1) ----
#pragma unroll
        for (int s = 0; s < 2; s++)
#pragma unroll
            for (int mi = 0; mi < 4; mi++)
#pragma unroll
                for (int nf = 0; nf < 4; nf++)
                    mma_f16(acc[mi][nf], a[s][mi],
                            b[s][nf >> 1][(nf & 1) * 2], b[s][nf >> 1][(nf & 1) * 2 + 1]);
    }

    // epilogue: (e,o) adjacent col pair per acc half
#pragma unroll
    for (int mi = 0; mi < 4; mi++) {
        int r_loc = wm * 64 + mi * 16 + (lane >> 2);
#pragma unroll
        for (int half = 0; half < 2; half++) {
            int mr = m0 + r_loc + half * 8;
            int bb = mr >> 11;
            int t  = mr & (T_DIM - 1);
#pragma unroll
            for (int nf = 0; nf < 4; nf++) {
                int n = n0 + wn * 32 + nf * 8 + (lane & 3) * 2;
                float e = acc[mi][nf][half * 2];
                float o = acc[mi][nf][half * 2 + 1];
                if (MODE == 3) {
                    *(float2*)&outf[(size_t)mr * N + n] = make_float2(e, o);
                } else {
                    // MODE 4: merged QKV; region uniform per CTA (128-aligned)
                    if (n < C_DIM) {
                        int hh = n >> 7, d = n & (HD - 1);
                        float cs = g_cos[t * 64 + (d >> 1)];
                        float sn = g_sin[t * 64 + (d >> 1)];
                        float oe = (e * cs - o * sn) * QK_SCALE;
                        float oo = (e * sn + o * cs) * QK_SCALE;
                        *(__half2*)&g_qh[(((size_t)bb * N_HEAD + hh) * T_DIM + t) * HD + d]
                            = __floats2half2_rn(oe, oo);
                    } else if (n < C_DIM + NKV_C) {
                        int nk = n - C_DIM;
                        int hh = nk >> 7, d = nk & (HD - 1);
                        float cs = g_cos[t * 64 + (d >> 1)];
                        float sn = g_sin[t * 64 + (d >> 1)];
                        float oe = e * cs - o * sn;
                        float oo = e * sn + o * cs;
                        *(__half2*)&g_kh[(((size_t)bb * N_KV + hh) * T_DIM + t) * HD + d]
                            = __floats2half2_rn(oe, oo);
                    } else {
                        int nv = n - C_DIM - NKV_C;
                        int hh = nv >> 7, d = nv & (HD - 1);
                        *(__half2*)&g_vh[(((size_t)bb * N_KV + hh) * T_DIM + t) * HD + d]
                            = __floats2half2_rn(e, o);
                    }
                }
            }
        }
    }
}

// ---------------------------------------------------------------------------
// fp16 tensor-core flash attention (FA2) -- unchanged (passing).
// ---------------------------------------------------------------------------
#define FSTR 136                      // halves per row
#define FQ_B (128 * FSTR * 2)         // 34816
#define FKV_B (64 * FSTR * 2)         // 17408
#define FL_SMEM (FQ_B + 2 * 2 * FKV_B)  // 104448

__global__ __launch_bounds__(256, 1)
void flash_tc(const int* __restrict__ amask, __half* __restrict__ oh)
{
    extern __shared__ __align__(16) char smem[];
    const uint32_t sb = smem_u32(smem);
    __shared__ uint32_t s_ms[2][2];

    const int tid = threadIdx.x;
    const int lane = tid & 31;
    const int wid = tid >> 5;
    const int qt = gridDim.x - 1 - blockIdx.x;   // LPT: heavy tiles first
    const int h  = blockIdx.y;
    const int b  = blockIdx.z;
    const int kvh = h & (N_KV - 1);

    const __half* qb = g_qh + (((size_t)b * N_HEAD + h) * T_DIM + qt * 128) * HD;
    const __half* kb = g_kh + (((size_t)b * N_KV + kvh) * T_DIM) * HD;
    const __half* vb = g_vh + (((size_t)b * N_KV + kvh) * T_DIM) * HD;

    // ---- stage Q tile ----
#pragma unroll
    for (int i = 0; i < 8; i++) {
        int idx = tid + i * 256;          // 0..2047
        int r = idx >> 4, c16 = idx & 15;
        cp_async16(sb + (uint32_t)(r * (FSTR * 2) + c16 * 16),
                   qb + (size_t)r * HD + c16 * 8);
    }
    cp_commit();

    auto load_tile = [&](int c) {
        uint32_t st = sb + FQ_B + (uint32_t)(c & 1) * (2 * FKV_B);
        const __half* ks = kb + (size_t)c * 64 * HD;
        const __half* vs = vb + (size_t)c * 64 * HD;
#pragma unroll
        for (int i = 0; i < 8; i++) {
            int idx = tid + i * 256;      // 0..2047
            int rem = idx & 1023;
            int r = rem >> 4, c16 = rem & 15;
            const __half* src = (idx < 1024) ? (ks + (size_t)r * HD + c16 * 8)
                                             : (vs + (size_t)r * HD + c16 * 8);
            uint32_t dst = st + (uint32_t)((idx < 1024) ? 0 : FKV_B)
                         + (uint32_t)(r * (FSTR * 2) + c16 * 16);
            cp_async16(dst, src);
        }
        cp_commit();
        if (tid < 64) {
            int v = amask[b * T_DIM + c * 64 + tid];
            uint32_t bal = __ballot_sync(0xffffffffu, v != 0);
            if ((tid & 31) == 0) s_ms[c & 1][tid >> 5] = bal;
        }
    };

    load_tile(0);
    cp_wait0();
    __syncthreads();

    // ---- Q fragments (resident) ----
    uint32_t qa[8][4];
    {
        const int a_row = lane & 15;
        const int a_col8 = (lane >> 4) * 8;
#pragma unroll
        for (int s = 0; s < 8; s++) {
            uint32_t addr = sb + (uint32_t)(
                (wid * 16 + a_row) * (FSTR * 2) + (s * 16 + a_col8) * 2);
            ldsm4(qa[s][0], qa[s][1], qa[s][2], qa[s][3], addr);
        }
    }

    float o[16][4];
#pragma unroll
    for (int nf = 0; nf < 16; nf++)
#pragma unroll
        for (int e = 0; e < 4; e++) o[nf][e] = 0.f;
    float m_i[2] = {-1e30f, -1e30f};
    float l_i[2] = {0.f, 0.f};

    const int b_row = (lane & 7) + ((lane & 16) >> 1);
    const int b_col8 = (lane & 8);
    const int row_in_warp = lane >> 2;
    const int qg_base = qt * 128 + wid * 16 + row_in_warp;   // rows: +0 and +8

    const int nkt = 2 * qt + 2;
    for (int kt = 0; kt < nkt; kt++) {
        cp_wait0();          // tile kt fully resident
        __syncthreads();     // visible to all; all warps past reads of tile kt-1
        if (kt + 1 < nkt) load_tile(kt + 1);   // overwrites kt-1's buffer (safe)

        uint32_t kBase = sb + FQ_B + (uint32_t)(kt & 1) * (2 * FKV_B);
        uint32_t vBase = kBase + FKV_B;

        // ---- S = Q @ K^T : warp computes 16 x 64 ----
        float s[8][4];
#pragma unroll
        for (int nb = 0; nb < 8; nb++)
#pragma unroll
            for (int e = 0; e < 4; e++) s[nb][e] = 0.f;

#pragma unroll
        for (int ks = 0; ks < 8; ks++) {
            uint32_t bb[4][4];
#pragma unroll
            for (int nb2 = 0; nb2 < 4; nb2++) {
                uint32_t addr = kBase + (uint32_t)(
                    (nb2 * 16 + b_row) * (FSTR * 2) + (ks * 16 + b_col8) * 2);
                ldsm4(bb[nb2][0], bb[nb2][1], bb[nb2][2], bb[nb2][3], addr);
            }
#pragma unroll
            for (int nb2 = 0; nb2 < 4; nb2++) {
                mma_f16(s[2 * nb2],     qa[ks], bb[nb2][0], bb[nb2][1]);
                mma_f16(s[2 * nb2 + 1], qa[ks], bb[nb2][2], bb[nb2][3]);
            }
        }

        // ---- mask ----
        const uint32_t w0 = s_ms[kt & 1][0], w1 = s_ms[kt & 1][1];
        const bool diag = (kt >= 2 * qt);
        const bool full_pad = (w0 == 0xffffffffu) && (w1 == 0xffffffffu);
        if (diag || !full_pad) {
#pragma unroll
            for (int nb = 0; nb < 8; nb++)
#pragma unroll
                for (int e = 0; e < 4; e++) {
                    int col = nb * 8 + (lane & 3) * 2 + (e & 1);
                    bool ok = ((col < 32 ? (w0 >> col) : (w1 >> (col - 32))) & 1u) != 0u;
                    if (diag)
                        ok = ok && (kt * 64 + col <= qg_base + (e >> 1) * 8);
                    if (!ok) s[nb][e] = -1e30f;
                }
        }

        // ---- online softmax (rows r and r+8 per thread) ----
        float mx[2] = {-1e30f, -1e30f};
#pragma unroll
        for (int nb = 0; nb < 8; nb++)
#pragma unroll
            for (int e = 0; e < 4; e++) mx[e >> 1] = fmaxf(mx[e >> 1], s[nb][e]);
#pragma unroll
        for (int i = 0; i < 2; i++) {
            mx[i] = fmaxf(mx[i], __shfl_xor_sync(0xffffffffu, mx[i], 1));
            mx[i] = fmaxf(mx[i], __shfl_xor_sync(0xffffffffu, mx[i], 2));
        }
        float alpha[2], rs[2] = {0.f, 0.f};
#pragma unroll
        for (int i = 0; i < 2; i++) {
            float mn = fmaxf(m_i[i], mx[i]);
            alpha[i] = exp2p((m_i[i] - mn) * LOG2E);
            m_i[i] = mn;
        }
#pragma unroll
        for (int nb = 0; nb < 8; nb++)
#pragma unroll
            for (int e = 0; e < 4; e++) {
                float p = exp2p((s[nb][e] - m_i[e >> 1]) * LOG2E);
                s[nb][e] = p;
                rs[e >> 1] += p;
            }
#pragma unroll
        for (int i = 0; i < 2; i++) {
            rs[i] += __shfl_xor_sync(0xffffffffu, rs[i], 1);
            rs[i] += __shfl_xor_sync(0xffffffffu, rs[i], 2);
            l_i[i] = l_i[i] * alpha[i] + rs[i];
        }

        // ---- O *= alpha ----
#pragma unroll
        for (int nf = 0; nf < 16; nf++) {
            o[nf][0] *= alpha[0]; o[nf][1] *= alpha[0];
            o[nf][2] *= alpha[1]; o[nf][3] *= alpha[1];
        }

        // ---- O += P @ V ----
#pragma unroll
        for (int kb = 0; kb < 4; kb++) {
            uint32_t pa[4];
            pa[0] = pack_h2(s[2 * kb][0], s[2 * kb][1]);
            pa[1] = pack_h2(s[2 * kb][2], s[2 * kb][3]);
            pa[2] = pack_h2(s[2 * kb + 1][0], s[2 * kb + 1][1]);
            pa[3] = pack_h2(s[2 * kb + 1][2], s[2 * kb + 1][3]);
#pragma unroll
            for (int nd2 = 0; nd2 < 8; nd2++) {
                uint32_t v0, v1, v2, v3;
                uint32_t addr = vBase + (uint32_t)(
                    (kb * 16 + (lane & 15)) * (FSTR * 2)
                    + (nd2 * 16 + (lane >> 4) * 8) * 2);
                ldsm4t(v0, v1, v2, v3, addr);
                mma_f16(o[2 * nd2],     pa, v0, v1);
                mma_f16(o[2 * nd2 + 1], pa, v2, v3);
            }
        }
    }

    // ---- epilogue: fp16 A for the O-projection ----
    float inv[2] = {1.f / l_i[0], 1.f / l_i[1]};
#pragma unroll
    for (int half = 0; half < 2; half++) {
        size_t row = (size_t)b * T_DIM + qt * 128 + wid * 16 + row_in_warp + half * 8;
#pragma unroll
        for (int nf = 0; nf < 16; nf++) {
            int cc = h * HD + nf * 8 + (lane & 3) * 2;
            *(__half2*)&oh[row * C_DIM + cc] = __floats2half2_rn(
                o[nf][half * 2] * inv[half], o[nf][half * 2 + 1] * inv[half]);
        }
    }
}

// ---------------------------------------------------------------------------
// Launch
// ---------------------------------------------------------------------------
extern "C" void kernel_launch(void* const* d_in, const int* in_sizes, int n_in,
                              void* d_out, int out_size)
{
    const float* x    = (const float*)d_in[0];
    const float* rope = (const float*)d_in[1];
    const int*   am   = (const int*)  d_in[2];
    const float* Wq   = (const float*)d_in[3];
    const float* Wk   = (const float*)d_in[4];
    const float* Wv   = (const float*)d_in[5];
    const float* Wo   = (const float*)d_in[6];
    float* out = (float*)d_out;

    __half *xh, *wqkv, *wo16, *ah;
    cudaGetSymbolAddress((void**)&xh, g_xh);
    cudaGetSymbolAddress((void**)&wqkv, g_wqkv);
    cudaGetSymbolAddress((void**)&wo16, g_wo16);
    cudaGetSymbolAddress((void**)&ah, g_ah);

    cudaFuncSetAttribute(gemm_f16<3>, cudaFuncAttributeMaxDynamicSharedMemorySize, GEMM_SMEM3);
    cudaFuncSetAttribute(gemm_f16<4>, cudaFuncAttributeMaxDynamicSharedMemorySize, GEMM_SMEM3);
    cudaFuncSetAttribute(flash_tc, cudaFuncAttributeMaxDynamicSharedMemorySize, FL_SMEM);

    // prep (launch indices 0..2)
    rope_tables_kernel<<<(T_DIM * 64 + 255) / 256, 256>>>(rope);
    conv_weights<<<((NQKV + C_DIM) * K_DIM / 8 + 255) / 256, 256>>>(Wq, Wk, Wv, Wo);
    to_f16<<<(M_TOT * K_DIM / 8 + 255) / 256, 256>>>(x, xh, M_TOT * K_DIM / 8);

    // merged QKV projection (index 3)
    gemm_f16<4><<<dim3(NQKV / 128, M_TOT / 128), 256, GEMM_SMEM3>>>(xh, wqkv, nullptr, NQKV);

    // attention (index 4)
    flash_tc<<<dim3(T_DIM / 128, N_HEAD, B_DIM), 256, FL_SMEM>>>(am, ah);

    // O projection (index 5 -- ncu -s 5 captures this GEMM)
    gemm_f16<3><<<dim3(C_DIM / 128, M_TOT / 128), 256, GEMM_SMEM3>>>(ah, wo16, out, C_DIM);
}